// round 8
// baseline (speedup 1.0000x reference)
#include <cuda_runtime.h>

#define N_NODES 100000
#define N_EDGES 800000
#define IN_DIM 128
#define HID_DIM 256
#define OUT_DIM 40

typedef unsigned long long u64;

// ---------------- scratch (static __device__ arrays; no allocs) ----------------
__device__ float4 g_agg1[N_NODES * IN_DIM / 4];    // 51.2 MB  neighbor-sum of x
__device__ float4 g_h[N_NODES * HID_DIM / 4];      // 102.4 MB hidden activations
__device__ float4 g_pq[N_NODES * 2 * OUT_DIM / 4]; // 32 MB    [p = h@W2l | q = h@W2r]
__device__ float4 g_agg2[N_NODES * OUT_DIM / 4];   // 16 MB    neighbor-sum of p
__device__ float  g_inv[N_NODES];                  // 1/max(deg,1)
__device__ int    g_cnt[N_NODES];

// ---------------- f32x2 helpers ----------------
__device__ __forceinline__ u64 rep2(float v) {
    u64 r;
    unsigned u = __float_as_uint(v);
    asm("mov.b64 %0, {%1, %2};" : "=l"(r) : "r"(u), "r"(u));
    return r;
}
__device__ __forceinline__ void ffma2(u64& d, u64 a, u64 b) {
    asm("fma.rn.f32x2 %0, %1, %2, %3;" : "=l"(d) : "l"(a), "l"(b), "l"(d));
}
__device__ __forceinline__ float2 unp2(u64 v) {
    unsigned lo, hi;
    asm("mov.b64 {%0, %1}, %2;" : "=r"(lo), "=r"(hi) : "l"(v));
    return make_float2(__uint_as_float(lo), __uint_as_float(hi));
}

// ---------------- zero scratch ----------------
__global__ void k_zero() {
    int i = blockIdx.x * blockDim.x + threadIdx.x;
    float4 z = make_float4(0.f, 0.f, 0.f, 0.f);
    if (i < N_NODES * IN_DIM / 4) g_agg1[i] = z;
    if (i < N_NODES * OUT_DIM / 4) g_agg2[i] = z;
    if (i < N_NODES) g_cnt[i] = 0;
}

// ---------------- edge pass 1: scatter-add x[src] -> agg1[dst], degree count ----------------
__global__ void k_edge1(const float4* __restrict__ x4, const int* __restrict__ ei) {
    int idx = blockIdx.x * blockDim.x + threadIdx.x;
    if (idx >= N_EDGES * 32) return;
    int e = idx >> 5;
    int c = idx & 31;
    int s = __ldg(&ei[e]);
    int d = __ldg(&ei[N_EDGES + e]);
    float4 v = x4[(size_t)s * 32 + c];
    float* a = ((float*)g_agg1) + (size_t)d * IN_DIM + c * 4;
    atomicAdd(a + 0, v.x);
    atomicAdd(a + 1, v.y);
    atomicAdd(a + 2, v.z);
    atomicAdd(a + 3, v.w);
    if (c == 0) atomicAdd(&g_cnt[d], 1);
}

__global__ void k_inv() {
    int i = blockIdx.x * blockDim.x + threadIdx.x;
    if (i < N_NODES) g_inv[i] = 1.0f / fmaxf((float)g_cnt[i], 1.0f);
}

// ---------------- GEMM1: h = relu((agg1*inv) @ W1l + x @ W1r + b1) ----------------
// BM=128, BN=128, BK=16, 256 threads, 8x8 per thread via f32x2 (row-paired accs).
__global__ __launch_bounds__(256) void k_gemm1(const float4* __restrict__ x4,
                                               const float4* __restrict__ W1l4,
                                               const float4* __restrict__ W1r4,
                                               const float4* __restrict__ b14) {
    __shared__ __align__(16) float As[16][128];  // [k][m]  8KB
    __shared__ __align__(16) float Bs[16][128];  // [k][n]  8KB

    int tid = threadIdx.x;
    int tx = tid & 15;          // col group (8 cols)
    int ty = tid >> 4;          // row group (8 rows)
    int rowBase = blockIdx.y * 128;
    int colBase = blockIdx.x * 128;

    // A loader: lm = row in tile, lk = base float4-index along k (covers lk, lk+1)
    int lm = tid & 127;
    int lk = (tid >> 7) * 2;
    int arow = rowBase + lm;
    bool aok = arow < N_NODES;
    float sc = aok ? g_inv[arow] : 0.f;

    // B loader: bk = k row, bc = float4 col; 2 halves of 64 cols
    int bk = tid >> 4;
    int bc = tid & 15;

    u64 acc[4][8];
#pragma unroll
    for (int i = 0; i < 4; i++)
#pragma unroll
        for (int j = 0; j < 8; j++) acc[i][j] = 0ull;

#pragma unroll
    for (int phase = 0; phase < 2; ++phase) {
        const float4* A4 = phase ? x4 : g_agg1;
        const float4* W4 = phase ? W1r4 : W1l4;
        for (int kt = 0; kt < IN_DIM; kt += 16) {
#pragma unroll
            for (int q = 0; q < 2; q++) {
                float4 v = make_float4(0.f, 0.f, 0.f, 0.f);
                if (aok) {
                    v = A4[(size_t)arow * 32 + (kt >> 2) + lk + q];
                    if (phase == 0) { v.x *= sc; v.y *= sc; v.z *= sc; v.w *= sc; }
                }
                int kb = (lk + q) * 4;
                As[kb + 0][lm] = v.x;
                As[kb + 1][lm] = v.y;
                As[kb + 2][lm] = v.z;
                As[kb + 3][lm] = v.w;
            }
#pragma unroll
            for (int half = 0; half < 2; half++) {
                float4 w = W4[(size_t)(kt + bk) * 64 + (colBase >> 2) + half * 16 + bc];
                *(float4*)&Bs[bk][half * 64 + bc * 4] = w;
            }
            __syncthreads();
#pragma unroll
            for (int k = 0; k < 16; ++k) {
                const u64* ap = (const u64*)&As[k][ty * 8];  // 4 row-pairs, 8B aligned
                u64 a0 = ap[0], a1 = ap[1], a2v = ap[2], a3 = ap[3];
                float4 w0 = *(const float4*)&Bs[k][tx * 8];
                float4 w1 = *(const float4*)&Bs[k][tx * 8 + 4];
                u64 b2[8];
                b2[0] = rep2(w0.x); b2[1] = rep2(w0.y);
                b2[2] = rep2(w0.z); b2[3] = rep2(w0.w);
                b2[4] = rep2(w1.x); b2[5] = rep2(w1.y);
                b2[6] = rep2(w1.z); b2[7] = rep2(w1.w);
#pragma unroll
                for (int j = 0; j < 8; j++) {
                    ffma2(acc[0][j], a0, b2[j]);
                    ffma2(acc[1][j], a1, b2[j]);
                    ffma2(acc[2][j], a2v, b2[j]);
                    ffma2(acc[3][j], a3, b2[j]);
                }
            }
            __syncthreads();
        }
    }

    // epilogue: bias + relu, rows (ty*8+2ri, +1), cols colBase + tx*8 .. +7
    int cb4 = (colBase >> 2) + tx * 2;
    float4 bb0 = b14[cb4];
    float4 bb1 = b14[cb4 + 1];
    float bv[8] = {bb0.x, bb0.y, bb0.z, bb0.w, bb1.x, bb1.y, bb1.z, bb1.w};
#pragma unroll
    for (int ri = 0; ri < 4; ri++) {
        int r0 = rowBase + ty * 8 + 2 * ri;
        float lo[8], hi[8];
#pragma unroll
        for (int j = 0; j < 8; j++) {
            float2 u = unp2(acc[ri][j]);
            lo[j] = fmaxf(u.x + bv[j], 0.f);
            hi[j] = fmaxf(u.y + bv[j], 0.f);
        }
        if (r0 < N_NODES) {
            g_h[(size_t)r0 * 64 + cb4]     = make_float4(lo[0], lo[1], lo[2], lo[3]);
            g_h[(size_t)r0 * 64 + cb4 + 1] = make_float4(lo[4], lo[5], lo[6], lo[7]);
        }
        if (r0 + 1 < N_NODES) {
            g_h[(size_t)(r0 + 1) * 64 + cb4]     = make_float4(hi[0], hi[1], hi[2], hi[3]);
            g_h[(size_t)(r0 + 1) * 64 + cb4 + 1] = make_float4(hi[4], hi[5], hi[6], hi[7]);
        }
    }
}

// ---------------- GEMM2: pq = h @ [W2l | W2r]  (N x 80, K=256) ----------------
// BM=128, BN=80, BK=16, 160 threads (16x10), 8x8 per thread via f32x2.
__global__ __launch_bounds__(160) void k_gemm2(const float4* __restrict__ W2l4,
                                               const float4* __restrict__ W2r4) {
    __shared__ __align__(16) float As[16][128];  // 8KB
    __shared__ __align__(16) float Bs[16][80];   // 5KB

    int tid = threadIdx.x;
    int tx = tid % 10;
    int ty = tid / 10;
    int rowBase = blockIdx.y * 128;

    u64 acc[4][8];
#pragma unroll
    for (int i = 0; i < 4; i++)
#pragma unroll
        for (int j = 0; j < 8; j++) acc[i][j] = 0ull;

    for (int kt = 0; kt < HID_DIM; kt += 16) {
        // A tile: 128 rows x 4 float4 = 512 slots
        for (int i = tid; i < 512; i += 160) {
            int m = i >> 2;
            int q = i & 3;
            int arow = rowBase + m;
            float4 v = make_float4(0.f, 0.f, 0.f, 0.f);
            if (arow < N_NODES) v = g_h[(size_t)arow * 64 + (kt >> 2) + q];
            As[q * 4 + 0][m] = v.x;
            As[q * 4 + 1][m] = v.y;
            As[q * 4 + 2][m] = v.z;
            As[q * 4 + 3][m] = v.w;
        }
        // B tile: 16 k x 20 float4 = 320 slots, [W2l | W2r]
        for (int i = tid; i < 320; i += 160) {
            int k = i / 20;
            int c4 = i % 20;
            float4 w;
            if (c4 < 10) w = W2l4[(size_t)(kt + k) * 10 + c4];
            else         w = W2r4[(size_t)(kt + k) * 10 + (c4 - 10)];
            *(float4*)&Bs[k][c4 * 4] = w;
        }
        __syncthreads();
#pragma unroll
        for (int k = 0; k < 16; ++k) {
            const u64* ap = (const u64*)&As[k][ty * 8];
            u64 a0 = ap[0], a1 = ap[1], a2v = ap[2], a3 = ap[3];
            float4 w0 = *(const float4*)&Bs[k][tx * 8];
            float4 w1 = *(const float4*)&Bs[k][tx * 8 + 4];
            u64 b2[8];
            b2[0] = rep2(w0.x); b2[1] = rep2(w0.y);
            b2[2] = rep2(w0.z); b2[3] = rep2(w0.w);
            b2[4] = rep2(w1.x); b2[5] = rep2(w1.y);
            b2[6] = rep2(w1.z); b2[7] = rep2(w1.w);
#pragma unroll
            for (int j = 0; j < 8; j++) {
                ffma2(acc[0][j], a0, b2[j]);
                ffma2(acc[1][j], a1, b2[j]);
                ffma2(acc[2][j], a2v, b2[j]);
                ffma2(acc[3][j], a3, b2[j]);
            }
        }
        __syncthreads();
    }

    // epilogue: cols tx*8..+7 -> float4 slots tx*2, tx*2+1 within row*20
#pragma unroll
    for (int ri = 0; ri < 4; ri++) {
        int r0 = rowBase + ty * 8 + 2 * ri;
        float lo[8], hi[8];
#pragma unroll
        for (int j = 0; j < 8; j++) {
            float2 u = unp2(acc[ri][j]);
            lo[j] = u.x;
            hi[j] = u.y;
        }
        if (r0 < N_NODES) {
            g_pq[(size_t)r0 * 20 + tx * 2]     = make_float4(lo[0], lo[1], lo[2], lo[3]);
            g_pq[(size_t)r0 * 20 + tx * 2 + 1] = make_float4(lo[4], lo[5], lo[6], lo[7]);
        }
        if (r0 + 1 < N_NODES) {
            g_pq[(size_t)(r0 + 1) * 20 + tx * 2]     = make_float4(hi[0], hi[1], hi[2], hi[3]);
            g_pq[(size_t)(r0 + 1) * 20 + tx * 2 + 1] = make_float4(hi[4], hi[5], hi[6], hi[7]);
        }
    }
}

// ---------------- edge pass 2: scatter-add p[src] -> agg2[dst] (40 floats) ----------------
__global__ void k_scatter2(const int* __restrict__ ei) {
    int idx = blockIdx.x * blockDim.x + threadIdx.x;
    if (idx >= N_EDGES * 10) return;
    int e = idx / 10;
    int c = idx % 10;
    int s = __ldg(&ei[e]);
    int d = __ldg(&ei[N_EDGES + e]);
    float4 v = g_pq[(size_t)s * 20 + c];  // p half = f4 slots 0..9
    float* a = ((float*)g_agg2) + (size_t)d * OUT_DIM + c * 4;
    atomicAdd(a + 0, v.x);
    atomicAdd(a + 1, v.y);
    atomicAdd(a + 2, v.z);
    atomicAdd(a + 3, v.w);
}

// ---------------- finalize: out = agg2*inv + b2 + q ----------------
__global__ void k_final(const float4* __restrict__ b24, float4* __restrict__ out4) {
    int idx = blockIdx.x * blockDim.x + threadIdx.x;
    if (idx >= N_NODES * 10) return;
    int row = idx / 10;
    int c = idx % 10;
    float inv = g_inv[row];
    float4 ag = g_agg2[(size_t)row * 10 + c];
    float4 q = g_pq[(size_t)row * 20 + 10 + c];  // q half = f4 slots 10..19
    float4 b = b24[c];
    float4 o;
    o.x = ag.x * inv + b.x + q.x;
    o.y = ag.y * inv + b.y + q.y;
    o.z = ag.z * inv + b.z + q.z;
    o.w = ag.w * inv + b.w + q.w;
    out4[idx] = o;
}

// ---------------- launch ----------------
extern "C" void kernel_launch(void* const* d_in, const int* in_sizes, int n_in,
                              void* d_out, int out_size) {
    const float4* x4 = (const float4*)d_in[0];
    const int* ei = (const int*)d_in[1];   // int32 (JAX x64 disabled)
    const float4* W1l4 = (const float4*)d_in[2];
    const float4* b14 = (const float4*)d_in[3];
    const float4* W1r4 = (const float4*)d_in[4];
    const float4* W2l4 = (const float4*)d_in[5];
    const float4* b24 = (const float4*)d_in[6];
    const float4* W2r4 = (const float4*)d_in[7];
    float4* out4 = (float4*)d_out;

    k_zero<<<(N_NODES * IN_DIM / 4 + 255) / 256, 256>>>();
    k_edge1<<<(N_EDGES * 32 + 255) / 256, 256>>>(x4, ei);
    k_inv<<<(N_NODES + 255) / 256, 256>>>();
    dim3 g1(2, (N_NODES + 127) / 128);
    k_gemm1<<<g1, 256>>>(x4, W1l4, W1r4, b14);
    dim3 g2(1, (N_NODES + 127) / 128);
    k_gemm2<<<g2, 160>>>(W2l4, W2r4);
    k_scatter2<<<(N_EDGES * 10 + 255) / 256, 256>>>(ei);
    k_final<<<(N_NODES * 10 + 255) / 256, 256>>>(b24, out4);
}

// round 12
// speedup vs baseline: 1.2010x; 1.2010x over previous
#include <cuda_runtime.h>

#define N_NODES 100000
#define N_EDGES 800000
#define IN_DIM 128
#define HID_DIM 256
#define OUT_DIM 40

// ---------------- scratch (static __device__ arrays; no allocs) ----------------
__device__ float4 g_agg1[N_NODES * IN_DIM / 4];    // 51.2 MB  neighbor-sum of x
__device__ float4 g_h[N_NODES * HID_DIM / 4];      // 102.4 MB hidden activations
__device__ float4 g_pq[N_NODES * 2 * OUT_DIM / 4]; // 32 MB    [p = h@W2l | q = h@W2r]
__device__ float4 g_agg2[N_NODES * OUT_DIM / 4];   // 16 MB    neighbor-sum of p
__device__ float  g_inv[N_NODES];                  // 1/max(deg,1)
__device__ int    g_cnt[N_NODES];

// ---------------- tf32 helpers (3xTF32 split for ~fp32 accuracy) ----------------
__device__ __forceinline__ void tf32_split(float x, unsigned& h, unsigned& l) {
    asm("cvt.rna.tf32.f32 %0, %1;" : "=r"(h) : "f"(x));
    float hf = __uint_as_float(h);   // tf32 pattern is a valid fp32 (low 13 bits zero)
    float d = x - hf;                // exact residual
    asm("cvt.rna.tf32.f32 %0, %1;" : "=r"(l) : "f"(d));
}

__device__ __forceinline__ void mma_tf32(float* c, const unsigned* a, const unsigned* b) {
    asm volatile(
        "mma.sync.aligned.m16n8k8.row.col.f32.tf32.tf32.f32 "
        "{%0,%1,%2,%3}, {%4,%5,%6,%7}, {%8,%9}, {%0,%1,%2,%3};"
        : "+f"(c[0]), "+f"(c[1]), "+f"(c[2]), "+f"(c[3])
        : "r"(a[0]), "r"(a[1]), "r"(a[2]), "r"(a[3]), "r"(b[0]), "r"(b[1]));
}

// ---------------- zero scratch ----------------
__global__ void k_zero() {
    int i = blockIdx.x * blockDim.x + threadIdx.x;
    float4 z = make_float4(0.f, 0.f, 0.f, 0.f);
    if (i < N_NODES * IN_DIM / 4) g_agg1[i] = z;
    if (i < N_NODES * OUT_DIM / 4) g_agg2[i] = z;
    if (i < N_NODES) g_cnt[i] = 0;
}

// ---------------- edge pass 1: scatter-add x[src] -> agg1[dst], degree count ----------------
__global__ void k_edge1(const float4* __restrict__ x4, const int* __restrict__ ei) {
    int idx = blockIdx.x * blockDim.x + threadIdx.x;
    if (idx >= N_EDGES * 32) return;
    int e = idx >> 5;
    int c = idx & 31;
    int s = __ldg(&ei[e]);
    int d = __ldg(&ei[N_EDGES + e]);
    float4 v = x4[(size_t)s * 32 + c];
    float* a = ((float*)g_agg1) + (size_t)d * IN_DIM + c * 4;
    atomicAdd(a + 0, v.x);
    atomicAdd(a + 1, v.y);
    atomicAdd(a + 2, v.z);
    atomicAdd(a + 3, v.w);
    if (c == 0) atomicAdd(&g_cnt[d], 1);
}

__global__ void k_inv() {
    int i = blockIdx.x * blockDim.x + threadIdx.x;
    if (i < N_NODES) g_inv[i] = 1.0f / fmaxf((float)g_cnt[i], 1.0f);
}

// ---------------- GEMM1 (tensor): h = relu((agg1*inv)@W1l + x@W1r + b1) ----------------
// BM=128, BN=64, BK=32. 256 threads = 8 warps (4 m x 2 n), warp tile 32x32.
// mma m16n8k8 tf32, 3xTF32 split. As[m][36], Bs[k][72] are bank-conflict-free.
__global__ __launch_bounds__(256) void k_gemm1(const float4* __restrict__ x4,
                                               const float4* __restrict__ W1l4,
                                               const float4* __restrict__ W1r4,
                                               const float4* __restrict__ b14) {
    __shared__ __align__(16) float As[128][36];
    __shared__ __align__(16) float Bs[32][72];

    int tid = threadIdx.x;
    int wid = tid >> 5, lane = tid & 31;
    int gid = lane >> 2, tig = lane & 3;
    int rowBase = blockIdx.y * 128;
    int colBase = blockIdx.x * 64;
    int warpM = (wid >> 1) * 32;
    int warpN = (wid & 1) * 32;

    float acc[2][4][4];
#pragma unroll
    for (int mt = 0; mt < 2; mt++)
#pragma unroll
        for (int nt = 0; nt < 4; nt++)
#pragma unroll
            for (int i = 0; i < 4; i++) acc[mt][nt][i] = 0.f;

#pragma unroll
    for (int phase = 0; phase < 2; ++phase) {
        const float4* A4 = phase ? x4 : g_agg1;
        const float4* W4 = phase ? W1r4 : W1l4;
        for (int kt = 0; kt < IN_DIM; kt += 32) {
            // stage A: 128 rows x 8 float4 (coalesced LDG, aligned STS.128)
#pragma unroll
            for (int i = 0; i < 4; i++) {
                int idx = tid + i * 256;
                int r = idx >> 3, q = idx & 7;
                int arow = rowBase + r;
                float4 v = make_float4(0.f, 0.f, 0.f, 0.f);
                if (arow < N_NODES) {
                    v = A4[(size_t)arow * 32 + (kt >> 2) + q];
                    if (phase == 0) {
                        float sc = g_inv[arow];
                        v.x *= sc; v.y *= sc; v.z *= sc; v.w *= sc;
                    }
                }
                *(float4*)&As[r][q * 4] = v;
            }
            // stage B: 32 k x 16 float4
#pragma unroll
            for (int i = 0; i < 2; i++) {
                int idx = tid + i * 256;
                int k = idx >> 4, c4 = idx & 15;
                float4 w = W4[(size_t)(kt + k) * 64 + (colBase >> 2) + c4];
                *(float4*)&Bs[k][c4 * 4] = w;
            }
            __syncthreads();
#pragma unroll
            for (int s = 0; s < 4; s++) {
                int k0 = s * 8 + tig;
                unsigned ah[8], al[8], bh[8], bl[8];
#pragma unroll
                for (int mt = 0; mt < 2; mt++) {
                    int m0 = warpM + mt * 16 + gid;
                    tf32_split(As[m0][k0],         ah[mt * 4 + 0], al[mt * 4 + 0]);
                    tf32_split(As[m0 + 8][k0],     ah[mt * 4 + 1], al[mt * 4 + 1]);
                    tf32_split(As[m0][k0 + 4],     ah[mt * 4 + 2], al[mt * 4 + 2]);
                    tf32_split(As[m0 + 8][k0 + 4], ah[mt * 4 + 3], al[mt * 4 + 3]);
                }
#pragma unroll
                for (int nt = 0; nt < 4; nt++) {
                    int n0 = warpN + nt * 8 + gid;
                    tf32_split(Bs[k0][n0],     bh[nt * 2 + 0], bl[nt * 2 + 0]);
                    tf32_split(Bs[k0 + 4][n0], bh[nt * 2 + 1], bl[nt * 2 + 1]);
                }
#pragma unroll
                for (int mt = 0; mt < 2; mt++)
#pragma unroll
                    for (int nt = 0; nt < 4; nt++) {
                        float* c = acc[mt][nt];
                        mma_tf32(c, &ah[mt * 4], &bh[nt * 2]);  // hi*hi
                        mma_tf32(c, &ah[mt * 4], &bl[nt * 2]);  // hi*lo
                        mma_tf32(c, &al[mt * 4], &bh[nt * 2]);  // lo*hi
                    }
            }
            __syncthreads();
        }
    }

    // epilogue: bias + relu, float2 stores
#pragma unroll
    for (int mt = 0; mt < 2; mt++) {
#pragma unroll
        for (int nt = 0; nt < 4; nt++) {
            int r0 = rowBase + warpM + mt * 16 + gid;
            int col = colBase + warpN + nt * 8 + 2 * tig;
            float2 bb = *(const float2*)((const float*)b14 + col);
            const float* c = acc[mt][nt];
            if (r0 < N_NODES) {
                float2 o = make_float2(fmaxf(c[0] + bb.x, 0.f), fmaxf(c[1] + bb.y, 0.f));
                *(float2*)(((float*)g_h) + (size_t)r0 * HID_DIM + col) = o;
            }
            if (r0 + 8 < N_NODES) {
                float2 o = make_float2(fmaxf(c[2] + bb.x, 0.f), fmaxf(c[3] + bb.y, 0.f));
                *(float2*)(((float*)g_h) + (size_t)(r0 + 8) * HID_DIM + col) = o;
            }
        }
    }
}

// ---------------- GEMM2 (tensor): pq = h @ [W2l | W2r]  (N x 80, K=256) ----------------
// BM=128, BN=80, BK=32. 256 threads = 8 warps (4 m x 2 n), warp tile 32x40.
__global__ __launch_bounds__(256) void k_gemm2(const float4* __restrict__ W2l4,
                                               const float4* __restrict__ W2r4) {
    __shared__ __align__(16) float As[128][36];
    __shared__ __align__(16) float Bs[32][88];

    int tid = threadIdx.x;
    int wid = tid >> 5, lane = tid & 31;
    int gid = lane >> 2, tig = lane & 3;
    int rowBase = blockIdx.y * 128;
    int warpM = (wid >> 1) * 32;
    int warpN = (wid & 1) * 40;

    float acc[2][5][4];
#pragma unroll
    for (int mt = 0; mt < 2; mt++)
#pragma unroll
        for (int nt = 0; nt < 5; nt++)
#pragma unroll
            for (int i = 0; i < 4; i++) acc[mt][nt][i] = 0.f;

    for (int kt = 0; kt < HID_DIM; kt += 32) {
        // stage A from g_h
#pragma unroll
        for (int i = 0; i < 4; i++) {
            int idx = tid + i * 256;
            int r = idx >> 3, q = idx & 7;
            int arow = rowBase + r;
            float4 v = make_float4(0.f, 0.f, 0.f, 0.f);
            if (arow < N_NODES) v = g_h[(size_t)arow * 64 + (kt >> 2) + q];
            *(float4*)&As[r][q * 4] = v;
        }
        // stage B: 32 k x 20 float4 ([W2l | W2r])
        for (int idx = tid; idx < 640; idx += 256) {
            int k = idx / 20, c4 = idx % 20;
            float4 w;
            if (c4 < 10) w = W2l4[(size_t)(kt + k) * 10 + c4];
            else         w = W2r4[(size_t)(kt + k) * 10 + (c4 - 10)];
            *(float4*)&Bs[k][c4 * 4] = w;
        }
        __syncthreads();
#pragma unroll
        for (int s = 0; s < 4; s++) {
            int k0 = s * 8 + tig;
            unsigned ah[8], al[8], bh[10], bl[10];
#pragma unroll
            for (int mt = 0; mt < 2; mt++) {
                int m0 = warpM + mt * 16 + gid;
                tf32_split(As[m0][k0],         ah[mt * 4 + 0], al[mt * 4 + 0]);
                tf32_split(As[m0 + 8][k0],     ah[mt * 4 + 1], al[mt * 4 + 1]);
                tf32_split(As[m0][k0 + 4],     ah[mt * 4 + 2], al[mt * 4 + 2]);
                tf32_split(As[m0 + 8][k0 + 4], ah[mt * 4 + 3], al[mt * 4 + 3]);
            }
#pragma unroll
            for (int nt = 0; nt < 5; nt++) {
                int n0 = warpN + nt * 8 + gid;
                tf32_split(Bs[k0][n0],     bh[nt * 2 + 0], bl[nt * 2 + 0]);
                tf32_split(Bs[k0 + 4][n0], bh[nt * 2 + 1], bl[nt * 2 + 1]);
            }
#pragma unroll
            for (int mt = 0; mt < 2; mt++)
#pragma unroll
                for (int nt = 0; nt < 5; nt++) {
                    float* c = acc[mt][nt];
                    mma_tf32(c, &ah[mt * 4], &bh[nt * 2]);
                    mma_tf32(c, &ah[mt * 4], &bl[nt * 2]);
                    mma_tf32(c, &al[mt * 4], &bh[nt * 2]);
                }
        }
        __syncthreads();
    }

#pragma unroll
    for (int mt = 0; mt < 2; mt++) {
#pragma unroll
        for (int nt = 0; nt < 5; nt++) {
            int r0 = rowBase + warpM + mt * 16 + gid;
            int col = warpN + nt * 8 + 2 * tig;   // 0..79 within [p|q]
            const float* c = acc[mt][nt];
            if (r0 < N_NODES)
                *(float2*)(((float*)g_pq) + (size_t)r0 * 80 + col) = make_float2(c[0], c[1]);
            if (r0 + 8 < N_NODES)
                *(float2*)(((float*)g_pq) + (size_t)(r0 + 8) * 80 + col) = make_float2(c[2], c[3]);
        }
    }
}

// ---------------- edge pass 2: scatter-add p[src] -> agg2[dst] (40 floats) ----------------
__global__ void k_scatter2(const int* __restrict__ ei) {
    int idx = blockIdx.x * blockDim.x + threadIdx.x;
    if (idx >= N_EDGES * 10) return;
    int e = idx / 10;
    int c = idx % 10;
    int s = __ldg(&ei[e]);
    int d = __ldg(&ei[N_EDGES + e]);
    float4 v = g_pq[(size_t)s * 20 + c];  // p half = f4 slots 0..9
    float* a = ((float*)g_agg2) + (size_t)d * OUT_DIM + c * 4;
    atomicAdd(a + 0, v.x);
    atomicAdd(a + 1, v.y);
    atomicAdd(a + 2, v.z);
    atomicAdd(a + 3, v.w);
}

// ---------------- finalize: out = agg2*inv + b2 + q ----------------
__global__ void k_final(const float4* __restrict__ b24, float4* __restrict__ out4) {
    int idx = blockIdx.x * blockDim.x + threadIdx.x;
    if (idx >= N_NODES * 10) return;
    int row = idx / 10;
    int c = idx % 10;
    float inv = g_inv[row];
    float4 ag = g_agg2[(size_t)row * 10 + c];
    float4 q = g_pq[(size_t)row * 20 + 10 + c];  // q half = f4 slots 10..19
    float4 b = b24[c];
    float4 o;
    o.x = ag.x * inv + b.x + q.x;
    o.y = ag.y * inv + b.y + q.y;
    o.z = ag.z * inv + b.z + q.z;
    o.w = ag.w * inv + b.w + q.w;
    out4[idx] = o;
}

// ---------------- launch ----------------
extern "C" void kernel_launch(void* const* d_in, const int* in_sizes, int n_in,
                              void* d_out, int out_size) {
    const float4* x4 = (const float4*)d_in[0];
    const int* ei = (const int*)d_in[1];   // int32 (JAX x64 disabled)
    const float4* W1l4 = (const float4*)d_in[2];
    const float4* b14 = (const float4*)d_in[3];
    const float4* W1r4 = (const float4*)d_in[4];
    const float4* W2l4 = (const float4*)d_in[5];
    const float4* b24 = (const float4*)d_in[6];
    const float4* W2r4 = (const float4*)d_in[7];
    float4* out4 = (float4*)d_out;

    k_zero<<<(N_NODES * IN_DIM / 4 + 255) / 256, 256>>>();
    k_edge1<<<(N_EDGES * 32 + 255) / 256, 256>>>(x4, ei);
    k_inv<<<(N_NODES + 255) / 256, 256>>>();
    dim3 g1(HID_DIM / 64, (N_NODES + 127) / 128);
    k_gemm1<<<g1, 256>>>(x4, W1l4, W1r4, b14);
    dim3 g2(1, (N_NODES + 127) / 128);
    k_gemm2<<<g2, 256>>>(W2l4, W2r4);
    k_scatter2<<<(N_EDGES * 10 + 255) / 256, 256>>>(ei);
    k_final<<<(N_NODES * 10 + 255) / 256, 256>>>(b24, out4);
}

// round 13
// speedup vs baseline: 1.5724x; 1.3093x over previous
#include <cuda_runtime.h>

#define N_NODES 100000
#define N_EDGES 800000
#define IN_DIM 128
#define HID_DIM 256
#define OUT_DIM 40

// ---------------- scratch (static __device__ arrays; no allocs) ----------------
__device__ float4 g_agg1[N_NODES * IN_DIM / 4];    // 51.2 MB  neighbor-sum of x
__device__ float4 g_h[N_NODES * HID_DIM / 4];      // 102.4 MB hidden activations
__device__ float4 g_pq[N_NODES * 2 * OUT_DIM / 4]; // 32 MB    [p = h@W2l | q = h@W2r]
__device__ float4 g_agg2[N_NODES * OUT_DIM / 4];   // 16 MB    neighbor-sum of p
__device__ float  g_inv[N_NODES];                  // 1/max(deg,1)
__device__ int    g_cnt[N_NODES];

// ---------------- tf32 helpers ----------------
__device__ __forceinline__ void tf32_split(float x, float& h, float& l) {
    unsigned hu, lu;
    asm("cvt.rna.tf32.f32 %0, %1;" : "=r"(hu) : "f"(x));
    float hf = __uint_as_float(hu);  // tf32 pattern is a valid fp32
    float d = x - hf;                // exact residual
    asm("cvt.rna.tf32.f32 %0, %1;" : "=r"(lu) : "f"(d));
    h = hf;
    l = __uint_as_float(lu);
}

__device__ __forceinline__ void mma_tf32(float* c, const unsigned* a, const unsigned* b) {
    asm volatile(
        "mma.sync.aligned.m16n8k8.row.col.f32.tf32.tf32.f32 "
        "{%0,%1,%2,%3}, {%4,%5,%6,%7}, {%8,%9}, {%0,%1,%2,%3};"
        : "+f"(c[0]), "+f"(c[1]), "+f"(c[2]), "+f"(c[3])
        : "r"(a[0]), "r"(a[1]), "r"(a[2]), "r"(a[3]), "r"(b[0]), "r"(b[1]));
}

__device__ __forceinline__ void red_add_v4(float* addr, float4 v) {
    asm volatile("red.global.add.v4.f32 [%0], {%1,%2,%3,%4};"
                 :: "l"(addr), "f"(v.x), "f"(v.y), "f"(v.z), "f"(v.w) : "memory");
}

// ---------------- zero scratch ----------------
__global__ void k_zero() {
    int i = blockIdx.x * blockDim.x + threadIdx.x;
    float4 z = make_float4(0.f, 0.f, 0.f, 0.f);
    if (i < N_NODES * IN_DIM / 4) g_agg1[i] = z;
    if (i < N_NODES * OUT_DIM / 4) g_agg2[i] = z;
    if (i < N_NODES) g_cnt[i] = 0;
}

// ---------------- edge pass 1: scatter-add x[src] -> agg1[dst], degree count ----------------
__global__ void k_edge1(const float4* __restrict__ x4, const int* __restrict__ ei) {
    int idx = blockIdx.x * blockDim.x + threadIdx.x;
    if (idx >= N_EDGES * 32) return;
    int e = idx >> 5;
    int c = idx & 31;
    int s = __ldg(&ei[e]);
    int d = __ldg(&ei[N_EDGES + e]);
    float4 v = x4[(size_t)s * 32 + c];
    float* a = ((float*)g_agg1) + (size_t)d * IN_DIM + c * 4;
    red_add_v4(a, v);
    if (c == 0) atomicAdd(&g_cnt[d], 1);
}

__global__ void k_inv() {
    int i = blockIdx.x * blockDim.x + threadIdx.x;
    if (i < N_NODES) g_inv[i] = 1.0f / fmaxf((float)g_cnt[i], 1.0f);
}

// ---------------- GEMM1 (tensor): h = relu((agg1*inv)@W1l + x@W1r + b1) ----------------
// BM=128, BN=64, BK=16. 256 threads = 8 warps (4m x 2n), warp tile 32x32.
// hi/lo tf32 split done ONCE at staging; mainloop is pure LDS+MMA.
__global__ __launch_bounds__(256) void k_gemm1(const float4* __restrict__ x4,
                                               const float4* __restrict__ W1l4,
                                               const float4* __restrict__ W1r4,
                                               const float4* __restrict__ b14) {
    __shared__ __align__(16) float As_hi[128][20], As_lo[128][20];  // 20KB
    __shared__ __align__(16) float Bs_hi[16][72], Bs_lo[16][72];    // 9KB

    int tid = threadIdx.x;
    int wid = tid >> 5, lane = tid & 31;
    int gid = lane >> 2, tig = lane & 3;
    int rowBase = blockIdx.y * 128;
    int colBase = blockIdx.x * 64;
    int warpM = (wid >> 1) * 32;
    int warpN = (wid & 1) * 32;

    float acc[2][4][4];
#pragma unroll
    for (int mt = 0; mt < 2; mt++)
#pragma unroll
        for (int nt = 0; nt < 4; nt++)
#pragma unroll
            for (int i = 0; i < 4; i++) acc[mt][nt][i] = 0.f;

#pragma unroll
    for (int phase = 0; phase < 2; ++phase) {
        const float4* A4 = phase ? x4 : g_agg1;
        const float4* W4 = phase ? W1r4 : W1l4;
        for (int kt = 0; kt < IN_DIM; kt += 16) {
            // stage A: 128 rows x 4 float4, split hi/lo at store
#pragma unroll
            for (int i = 0; i < 2; i++) {
                int idx = tid + i * 256;
                int r = idx >> 2, q = idx & 3;
                int arow = rowBase + r;
                float4 v = make_float4(0.f, 0.f, 0.f, 0.f);
                if (arow < N_NODES) {
                    v = A4[(size_t)arow * 32 + (kt >> 2) + q];
                    if (phase == 0) {
                        float sc = g_inv[arow];
                        v.x *= sc; v.y *= sc; v.z *= sc; v.w *= sc;
                    }
                }
                float h0, l0, h1, l1, h2, l2, h3, l3;
                tf32_split(v.x, h0, l0); tf32_split(v.y, h1, l1);
                tf32_split(v.z, h2, l2); tf32_split(v.w, h3, l3);
                int kb = q * 4;
                As_hi[r][kb] = h0; As_hi[r][kb + 1] = h1; As_hi[r][kb + 2] = h2; As_hi[r][kb + 3] = h3;
                As_lo[r][kb] = l0; As_lo[r][kb + 1] = l1; As_lo[r][kb + 2] = l2; As_lo[r][kb + 3] = l3;
            }
            // stage B: 16 k x 16 float4
            {
                int k = tid >> 4, c4 = tid & 15;
                float4 w = W4[(size_t)(kt + k) * 64 + (colBase >> 2) + c4];
                float h0, l0, h1, l1, h2, l2, h3, l3;
                tf32_split(w.x, h0, l0); tf32_split(w.y, h1, l1);
                tf32_split(w.z, h2, l2); tf32_split(w.w, h3, l3);
                int nb = c4 * 4;
                Bs_hi[k][nb] = h0; Bs_hi[k][nb + 1] = h1; Bs_hi[k][nb + 2] = h2; Bs_hi[k][nb + 3] = h3;
                Bs_lo[k][nb] = l0; Bs_lo[k][nb + 1] = l1; Bs_lo[k][nb + 2] = l2; Bs_lo[k][nb + 3] = l3;
            }
            __syncthreads();
#pragma unroll
            for (int s = 0; s < 2; s++) {
                int k0 = s * 8 + tig;
                unsigned ah[8], al[8], bh[8], bl[8];
#pragma unroll
                for (int mt = 0; mt < 2; mt++) {
                    int m0 = warpM + mt * 16 + gid;
                    ah[mt*4+0] = __float_as_uint(As_hi[m0][k0]);
                    ah[mt*4+1] = __float_as_uint(As_hi[m0 + 8][k0]);
                    ah[mt*4+2] = __float_as_uint(As_hi[m0][k0 + 4]);
                    ah[mt*4+3] = __float_as_uint(As_hi[m0 + 8][k0 + 4]);
                    al[mt*4+0] = __float_as_uint(As_lo[m0][k0]);
                    al[mt*4+1] = __float_as_uint(As_lo[m0 + 8][k0]);
                    al[mt*4+2] = __float_as_uint(As_lo[m0][k0 + 4]);
                    al[mt*4+3] = __float_as_uint(As_lo[m0 + 8][k0 + 4]);
                }
#pragma unroll
                for (int nt = 0; nt < 4; nt++) {
                    int n0 = warpN + nt * 8 + gid;
                    bh[nt*2+0] = __float_as_uint(Bs_hi[k0][n0]);
                    bh[nt*2+1] = __float_as_uint(Bs_hi[k0 + 4][n0]);
                    bl[nt*2+0] = __float_as_uint(Bs_lo[k0][n0]);
                    bl[nt*2+1] = __float_as_uint(Bs_lo[k0 + 4][n0]);
                }
#pragma unroll
                for (int mt = 0; mt < 2; mt++)
#pragma unroll
                    for (int nt = 0; nt < 4; nt++) {
                        float* c = acc[mt][nt];
                        mma_tf32(c, &ah[mt * 4], &bh[nt * 2]);  // hi*hi
                        mma_tf32(c, &ah[mt * 4], &bl[nt * 2]);  // hi*lo
                        mma_tf32(c, &al[mt * 4], &bh[nt * 2]);  // lo*hi
                    }
            }
            __syncthreads();
        }
    }

    // epilogue: bias + relu, float2 stores
#pragma unroll
    for (int mt = 0; mt < 2; mt++) {
#pragma unroll
        for (int nt = 0; nt < 4; nt++) {
            int r0 = rowBase + warpM + mt * 16 + gid;
            int col = colBase + warpN + nt * 8 + 2 * tig;
            float2 bb = *(const float2*)((const float*)b14 + col);
            const float* c = acc[mt][nt];
            if (r0 < N_NODES) {
                float2 o = make_float2(fmaxf(c[0] + bb.x, 0.f), fmaxf(c[1] + bb.y, 0.f));
                *(float2*)(((float*)g_h) + (size_t)r0 * HID_DIM + col) = o;
            }
            if (r0 + 8 < N_NODES) {
                float2 o = make_float2(fmaxf(c[2] + bb.x, 0.f), fmaxf(c[3] + bb.y, 0.f));
                *(float2*)(((float*)g_h) + (size_t)(r0 + 8) * HID_DIM + col) = o;
            }
        }
    }
}

// ---------------- GEMM2 (tensor): pq = h @ [W2l | W2r]  (N x 80, K=256) ----------------
// BM=128, BN=80, BK=16. 256 threads = 8 warps (4m x 2n), warp tile 32x40.
__global__ __launch_bounds__(256) void k_gemm2(const float4* __restrict__ W2l4,
                                               const float4* __restrict__ W2r4) {
    __shared__ __align__(16) float As_hi[128][20], As_lo[128][20];  // 20KB
    __shared__ __align__(16) float Bs_hi[16][88], Bs_lo[16][88];    // 11KB

    int tid = threadIdx.x;
    int wid = tid >> 5, lane = tid & 31;
    int gid = lane >> 2, tig = lane & 3;
    int rowBase = blockIdx.y * 128;
    int warpM = (wid >> 1) * 32;
    int warpN = (wid & 1) * 40;

    float acc[2][5][4];
#pragma unroll
    for (int mt = 0; mt < 2; mt++)
#pragma unroll
        for (int nt = 0; nt < 5; nt++)
#pragma unroll
            for (int i = 0; i < 4; i++) acc[mt][nt][i] = 0.f;

    for (int kt = 0; kt < HID_DIM; kt += 16) {
        // stage A from g_h (split at store)
#pragma unroll
        for (int i = 0; i < 2; i++) {
            int idx = tid + i * 256;
            int r = idx >> 2, q = idx & 3;
            int arow = rowBase + r;
            float4 v = make_float4(0.f, 0.f, 0.f, 0.f);
            if (arow < N_NODES) v = g_h[(size_t)arow * 64 + (kt >> 2) + q];
            float h0, l0, h1, l1, h2, l2, h3, l3;
            tf32_split(v.x, h0, l0); tf32_split(v.y, h1, l1);
            tf32_split(v.z, h2, l2); tf32_split(v.w, h3, l3);
            int kb = q * 4;
            As_hi[r][kb] = h0; As_hi[r][kb + 1] = h1; As_hi[r][kb + 2] = h2; As_hi[r][kb + 3] = h3;
            As_lo[r][kb] = l0; As_lo[r][kb + 1] = l1; As_lo[r][kb + 2] = l2; As_lo[r][kb + 3] = l3;
        }
        // stage B: 16 k x 20 float4 ([W2l | W2r])
        for (int idx = tid; idx < 320; idx += 256) {
            int k = idx / 20, c4 = idx % 20;
            float4 w;
            if (c4 < 10) w = W2l4[(size_t)(kt + k) * 10 + c4];
            else         w = W2r4[(size_t)(kt + k) * 10 + (c4 - 10)];
            float h0, l0, h1, l1, h2, l2, h3, l3;
            tf32_split(w.x, h0, l0); tf32_split(w.y, h1, l1);
            tf32_split(w.z, h2, l2); tf32_split(w.w, h3, l3);
            int nb = c4 * 4;
            Bs_hi[k][nb] = h0; Bs_hi[k][nb + 1] = h1; Bs_hi[k][nb + 2] = h2; Bs_hi[k][nb + 3] = h3;
            Bs_lo[k][nb] = l0; Bs_lo[k][nb + 1] = l1; Bs_lo[k][nb + 2] = l2; Bs_lo[k][nb + 3] = l3;
        }
        __syncthreads();
#pragma unroll
        for (int s = 0; s < 2; s++) {
            int k0 = s * 8 + tig;
            unsigned ah[8], al[8], bh[10], bl[10];
#pragma unroll
            for (int mt = 0; mt < 2; mt++) {
                int m0 = warpM + mt * 16 + gid;
                ah[mt*4+0] = __float_as_uint(As_hi[m0][k0]);
                ah[mt*4+1] = __float_as_uint(As_hi[m0 + 8][k0]);
                ah[mt*4+2] = __float_as_uint(As_hi[m0][k0 + 4]);
                ah[mt*4+3] = __float_as_uint(As_hi[m0 + 8][k0 + 4]);
                al[mt*4+0] = __float_as_uint(As_lo[m0][k0]);
                al[mt*4+1] = __float_as_uint(As_lo[m0 + 8][k0]);
                al[mt*4+2] = __float_as_uint(As_lo[m0][k0 + 4]);
                al[mt*4+3] = __float_as_uint(As_lo[m0 + 8][k0 + 4]);
            }
#pragma unroll
            for (int nt = 0; nt < 5; nt++) {
                int n0 = warpN + nt * 8 + gid;
                bh[nt*2+0] = __float_as_uint(Bs_hi[k0][n0]);
                bh[nt*2+1] = __float_as_uint(Bs_hi[k0 + 4][n0]);
                bl[nt*2+0] = __float_as_uint(Bs_lo[k0][n0]);
                bl[nt*2+1] = __float_as_uint(Bs_lo[k0 + 4][n0]);
            }
#pragma unroll
            for (int mt = 0; mt < 2; mt++)
#pragma unroll
                for (int nt = 0; nt < 5; nt++) {
                    float* c = acc[mt][nt];
                    mma_tf32(c, &ah[mt * 4], &bh[nt * 2]);
                    mma_tf32(c, &ah[mt * 4], &bl[nt * 2]);
                    mma_tf32(c, &al[mt * 4], &bh[nt * 2]);
                }
        }
        __syncthreads();
    }

#pragma unroll
    for (int mt = 0; mt < 2; mt++) {
#pragma unroll
        for (int nt = 0; nt < 5; nt++) {
            int r0 = rowBase + warpM + mt * 16 + gid;
            int col = warpN + nt * 8 + 2 * tig;   // 0..79 within [p|q]
            const float* c = acc[mt][nt];
            if (r0 < N_NODES)
                *(float2*)(((float*)g_pq) + (size_t)r0 * 80 + col) = make_float2(c[0], c[1]);
            if (r0 + 8 < N_NODES)
                *(float2*)(((float*)g_pq) + (size_t)(r0 + 8) * 80 + col) = make_float2(c[2], c[3]);
        }
    }
}

// ---------------- edge pass 2: scatter-add p[src] -> agg2[dst] (40 floats) ----------------
__global__ void k_scatter2(const int* __restrict__ ei) {
    int idx = blockIdx.x * blockDim.x + threadIdx.x;
    if (idx >= N_EDGES * 10) return;
    int e = idx / 10;
    int c = idx % 10;
    int s = __ldg(&ei[e]);
    int d = __ldg(&ei[N_EDGES + e]);
    float4 v = g_pq[(size_t)s * 20 + c];  // p half = f4 slots 0..9
    float* a = ((float*)g_agg2) + (size_t)d * OUT_DIM + c * 4;
    red_add_v4(a, v);
}

// ---------------- finalize: out = agg2*inv + b2 + q ----------------
__global__ void k_final(const float4* __restrict__ b24, float4* __restrict__ out4) {
    int idx = blockIdx.x * blockDim.x + threadIdx.x;
    if (idx >= N_NODES * 10) return;
    int row = idx / 10;
    int c = idx % 10;
    float inv = g_inv[row];
    float4 ag = g_agg2[(size_t)row * 10 + c];
    float4 q = g_pq[(size_t)row * 20 + 10 + c];  // q half = f4 slots 10..19
    float4 b = b24[c];
    float4 o;
    o.x = ag.x * inv + b.x + q.x;
    o.y = ag.y * inv + b.y + q.y;
    o.z = ag.z * inv + b.z + q.z;
    o.w = ag.w * inv + b.w + q.w;
    out4[idx] = o;
}

// ---------------- launch ----------------
extern "C" void kernel_launch(void* const* d_in, const int* in_sizes, int n_in,
                              void* d_out, int out_size) {
    const float4* x4 = (const float4*)d_in[0];
    const int* ei = (const int*)d_in[1];   // int32 (JAX x64 disabled)
    const float4* W1l4 = (const float4*)d_in[2];
    const float4* b14 = (const float4*)d_in[3];
    const float4* W1r4 = (const float4*)d_in[4];
    const float4* W2l4 = (const float4*)d_in[5];
    const float4* b24 = (const float4*)d_in[6];
    const float4* W2r4 = (const float4*)d_in[7];
    float4* out4 = (float4*)d_out;

    k_zero<<<(N_NODES * IN_DIM / 4 + 255) / 256, 256>>>();
    k_edge1<<<(N_EDGES * 32 + 255) / 256, 256>>>(x4, ei);
    k_inv<<<(N_NODES + 255) / 256, 256>>>();
    dim3 g1(HID_DIM / 64, (N_NODES + 127) / 128);
    k_gemm1<<<g1, 256>>>(x4, W1l4, W1r4, b14);
    dim3 g2(1, (N_NODES + 127) / 128);
    k_gemm2<<<g2, 256>>>(W2l4, W2r4);
    k_scatter2<<<(N_EDGES * 10 + 255) / 256, 256>>>(ei);
    k_final<<<(N_NODES * 10 + 255) / 256, 256>>>(b24, out4);
}